// round 7
// baseline (speedup 1.0000x reference)
#include <cuda_runtime.h>
#include <cstdint>
#include <float.h>

// Problem constants
#define Bn 32768
#define Ln 4
#define Kn 2048
#define Dn 512

// Output layout (float32, flattened tuple in return order):
//   output [B,L], r [B,L,D], e [B,L,D], z_hat [B,D], count [1]
constexpr size_t OFF_OUT = 0;
constexpr size_t OFF_R   = (size_t)Bn * Ln;                       // 131072
constexpr size_t OFF_E   = OFF_R + (size_t)Bn * Ln * Dn;          // 67239936
constexpr size_t OFF_Z   = OFF_E + (size_t)Bn * Ln * Dn;          // 134348800
constexpr size_t OFF_CNT = OFF_Z + (size_t)Bn * Dn;               // 151126016

// Scratch (device globals; no allocations allowed)
__device__ int   g_idx[Bn * Ln];
__device__ int   g_hist[Ln * Kn];
__device__ float g_cnorm[Ln * Kn];
__device__ float g_xnorm[Bn];

// ---------------- packed f32x2 helpers ----------------
__device__ __forceinline__ unsigned long long pack2(float a, float b) {
    unsigned long long r;
    asm("mov.b64 %0, {%1, %2};" : "=l"(r) : "f"(a), "f"(b));
    return r;
}
__device__ __forceinline__ unsigned long long fma2(unsigned long long a,
                                                   unsigned long long b,
                                                   unsigned long long c) {
    unsigned long long d;
    asm("fma.rn.f32x2 %0, %1, %2, %3;" : "=l"(d) : "l"(a), "l"(b), "l"(c));
    return d;
}
__device__ __forceinline__ void unpack2(unsigned long long p, float& a, float& b) {
    asm("mov.b64 {%0, %1}, %2;" : "=f"(a), "=f"(b) : "l"(p));
}

// ---------------- XLA-GPU-style f32 row-norm of a 512-float row ----------------
// (passed bitwise in R3 — do not touch)
__device__ __forceinline__ float xla_rownorm512(const float* __restrict__ row,
                                                float* __restrict__ sh8) {
    int t = threadIdx.x;           // 0..255
    int lane = t & 31;
    int w = t >> 5;                // 0..7
    float2 e = *(const float2*)(row + 2 * t);
    float p = __fadd_rn(__fmul_rn(e.x, e.x), __fmul_rn(e.y, e.y));
#pragma unroll
    for (int off = 16; off; off >>= 1)
        p = __fadd_rn(p, __shfl_down_sync(0xFFFFFFFFu, p, off));
    if (lane == 0) sh8[w] = p;
    __syncthreads();
    float s = 0.0f;
    if (w == 0) {
        s = (lane < 8) ? sh8[lane] : 0.0f;
#pragma unroll
        for (int off = 16; off; off >>= 1)
            s = __fadd_rn(s, __shfl_down_sync(0xFFFFFFFFu, s, off));
    }
    return s;   // valid in thread 0 only
}

// ---------------- prep: codebook norms (XLA-order f32) + zero histogram ----------------
__global__ void __launch_bounds__(256) prep_kernel(const float* __restrict__ cb) {
    __shared__ float sh8[8];
    int code = blockIdx.x;                 // 0 .. L*K-1
    float s = xla_rownorm512(cb + (size_t)code * Dn, sh8);
    if (threadIdx.x == 0) {
        g_cnorm[code] = s;
        g_hist[code] = 0;
    }
}

// ---------------- per-level row norms (XLA-order f32) ----------------
__global__ void __launch_bounds__(256) xnorm_kernel(const float* __restrict__ out, int level) {
    __shared__ float sh8[8];
    int b = blockIdx.x;                    // 0 .. B-1
    float s = xla_rownorm512(out + OFF_R + ((size_t)b * Ln + level) * Dn, sh8);
    if (threadIdx.x == 0) g_xnorm[b] = s;
}

// ---------------- r[:,0,:] = x ----------------
__global__ void copy_r0_kernel(const float* __restrict__ x, float* __restrict__ out) {
    size_t t = (size_t)blockIdx.x * blockDim.x + threadIdx.x;  // B*D/4 threads
    int b = (int)(t >> 7);
    int d4 = ((int)t & 127) << 2;
    float4 v = *(const float4*)(x + (size_t)b * Dn + d4);
    *(float4*)(out + OFF_R + (size_t)b * Ln * Dn + d4) = v;
}

// ---------------- fused distance + argmin per level ----------------
constexpr int TM  = 128;   // rows per block
constexpr int TN  = 128;   // code chunk
constexpr int DKc = 8;     // D step per smem stage
constexpr int NIT = Dn / DKc;        // 64
constexpr int XSP_STRIDE = TM + 2;   // 130, ulonglong units (16B-aligned rows: 130*8=1040)
constexpr int CS_STRIDE  = TN + 4;   // 132 floats (16B-aligned rows: 132*4=528)

__global__ void __launch_bounds__(256, 2)
argmin_kernel(float* __restrict__ out_base, const float* __restrict__ cb, int level) {
    // x tile stored PRE-PACKED as {x,x} pairs -> LDS yields FMA2 operands directly
    __shared__ __align__(16) unsigned long long xsp[2][DKc * XSP_STRIDE]; // 2*8*130*8 = 16640 B
    __shared__ __align__(16) float              cs [2][DKc * CS_STRIDE];  // 2*8*132*4 =  8448 B

    const int tid = threadIdx.x;
    const int m0  = blockIdx.x * TM;
    const int tr  = tid & 15;          // row group: rows tr*8 .. tr*8+7
    const int tc  = tid >> 4;          // code group: codes tc*8 .. tc*8+7
    const int frow = tid >> 1;         // fill row/code 0..127
    const int fc4  = (tid & 1) << 2;   // fill col 0 or 4

    const float* __restrict__ cbl = cb + (size_t)level * Kn * Dn;
    const float* __restrict__ cn  = g_cnorm + level * Kn;
    const float* __restrict__ xrow = out_base + OFF_R + (size_t)level * Dn
                                   + ((size_t)(m0 + frow)) * (Ln * Dn) + fc4;

    float xn[8];
#pragma unroll
    for (int r = 0; r < 8; r++) xn[r] = g_xnorm[m0 + tr * 8 + r];

    float best[8];
    int   bidx[8];
#pragma unroll
    for (int r = 0; r < 8; r++) { best[r] = FLT_MAX; bidx[r] = 0; }

#pragma unroll 1
    for (int kc = 0; kc < Kn; kc += TN) {
        const float* __restrict__ crow = cbl + (size_t)(kc + frow) * Dn + fc4;

        unsigned long long acc[8][4];
#pragma unroll
        for (int r = 0; r < 8; r++)
#pragma unroll
            for (int p = 0; p < 4; p++) acc[r][p] = 0ULL;

        // ---- stage tile 0 + prefetch tile 1 ----
        float4 xg = *(const float4*)(xrow);
        float4 cg = *(const float4*)(crow);
        {
            unsigned long long* xd = &xsp[0][0];
            float* cd = &cs[0][0];
            xd[(fc4 + 0) * XSP_STRIDE + frow] = pack2(xg.x, xg.x);
            xd[(fc4 + 1) * XSP_STRIDE + frow] = pack2(xg.y, xg.y);
            xd[(fc4 + 2) * XSP_STRIDE + frow] = pack2(xg.z, xg.z);
            xd[(fc4 + 3) * XSP_STRIDE + frow] = pack2(xg.w, xg.w);
            cd[(fc4 + 0) * CS_STRIDE + frow] = cg.x;
            cd[(fc4 + 1) * CS_STRIDE + frow] = cg.y;
            cd[(fc4 + 2) * CS_STRIDE + frow] = cg.z;
            cd[(fc4 + 3) * CS_STRIDE + frow] = cg.w;
        }
        xg = *(const float4*)(xrow + DKc);
        cg = *(const float4*)(crow + DKc);
        __syncthreads();

#pragma unroll 1
        for (int it = 0; it < NIT; it++) {
            const int cur = it & 1;
            // store prefetched tile (it+1) into the other buffer (free since end of it-1)
            if (it + 1 < NIT) {
                unsigned long long* xd = &xsp[cur ^ 1][0];
                float* cd = &cs[cur ^ 1][0];
                xd[(fc4 + 0) * XSP_STRIDE + frow] = pack2(xg.x, xg.x);
                xd[(fc4 + 1) * XSP_STRIDE + frow] = pack2(xg.y, xg.y);
                xd[(fc4 + 2) * XSP_STRIDE + frow] = pack2(xg.z, xg.z);
                xd[(fc4 + 3) * XSP_STRIDE + frow] = pack2(xg.w, xg.w);
                cd[(fc4 + 0) * CS_STRIDE + frow] = cg.x;
                cd[(fc4 + 1) * CS_STRIDE + frow] = cg.y;
                cd[(fc4 + 2) * CS_STRIDE + frow] = cg.z;
                cd[(fc4 + 3) * CS_STRIDE + frow] = cg.w;
            }
            // prefetch tile (it+2)
            if (it + 2 < NIT) {
                xg = *(const float4*)(xrow + (it + 2) * DKc);
                cg = *(const float4*)(crow + (it + 2) * DKc);
            }
            // compute on current buffer: 8 kk x (8 rows x 8 codes)
#pragma unroll
            for (int kk = 0; kk < DKc; kk++) {
                const unsigned long long* xp = &xsp[cur][kk * XSP_STRIDE + tr * 8];
                ulonglong2 xv01 = *(const ulonglong2*)(xp + 0);
                ulonglong2 xv23 = *(const ulonglong2*)(xp + 2);
                ulonglong2 xv45 = *(const ulonglong2*)(xp + 4);
                ulonglong2 xv67 = *(const ulonglong2*)(xp + 6);
                const float* cp = &cs[cur][kk * CS_STRIDE + tc * 8];
                ulonglong2 cc01 = *(const ulonglong2*)(cp + 0);
                ulonglong2 cc23 = *(const ulonglong2*)(cp + 4);
                acc[0][0] = fma2(xv01.x, cc01.x, acc[0][0]);
                acc[0][1] = fma2(xv01.x, cc01.y, acc[0][1]);
                acc[0][2] = fma2(xv01.x, cc23.x, acc[0][2]);
                acc[0][3] = fma2(xv01.x, cc23.y, acc[0][3]);
                acc[1][0] = fma2(xv01.y, cc01.x, acc[1][0]);
                acc[1][1] = fma2(xv01.y, cc01.y, acc[1][1]);
                acc[1][2] = fma2(xv01.y, cc23.x, acc[1][2]);
                acc[1][3] = fma2(xv01.y, cc23.y, acc[1][3]);
                acc[2][0] = fma2(xv23.x, cc01.x, acc[2][0]);
                acc[2][1] = fma2(xv23.x, cc01.y, acc[2][1]);
                acc[2][2] = fma2(xv23.x, cc23.x, acc[2][2]);
                acc[2][3] = fma2(xv23.x, cc23.y, acc[2][3]);
                acc[3][0] = fma2(xv23.y, cc01.x, acc[3][0]);
                acc[3][1] = fma2(xv23.y, cc01.y, acc[3][1]);
                acc[3][2] = fma2(xv23.y, cc23.x, acc[3][2]);
                acc[3][3] = fma2(xv23.y, cc23.y, acc[3][3]);
                acc[4][0] = fma2(xv45.x, cc01.x, acc[4][0]);
                acc[4][1] = fma2(xv45.x, cc01.y, acc[4][1]);
                acc[4][2] = fma2(xv45.x, cc23.x, acc[4][2]);
                acc[4][3] = fma2(xv45.x, cc23.y, acc[4][3]);
                acc[5][0] = fma2(xv45.y, cc01.x, acc[5][0]);
                acc[5][1] = fma2(xv45.y, cc01.y, acc[5][1]);
                acc[5][2] = fma2(xv45.y, cc23.x, acc[5][2]);
                acc[5][3] = fma2(xv45.y, cc23.y, acc[5][3]);
                acc[6][0] = fma2(xv67.x, cc01.x, acc[6][0]);
                acc[6][1] = fma2(xv67.x, cc01.y, acc[6][1]);
                acc[6][2] = fma2(xv67.x, cc23.x, acc[6][2]);
                acc[6][3] = fma2(xv67.x, cc23.y, acc[6][3]);
                acc[7][0] = fma2(xv67.y, cc01.x, acc[7][0]);
                acc[7][1] = fma2(xv67.y, cc01.y, acc[7][1]);
                acc[7][2] = fma2(xv67.y, cc23.x, acc[7][2]);
                acc[7][3] = fma2(xv67.y, cc23.y, acc[7][3]);
            }
            __syncthreads();
        }

        // fold chunk scores: d = fl( fl(xx - fl(2*m)) + cc ), first-index tie-break
#pragma unroll
        for (int p = 0; p < 4; p++) {
            int k0 = kc + tc * 8 + 2 * p;
            float2 cnv = *(const float2*)(cn + k0);
#pragma unroll
            for (int r = 0; r < 8; r++) {
                float m0v, m1v;
                unpack2(acc[r][p], m0v, m1v);
                float v0 = __fadd_rn(__fsub_rn(xn[r], __fmul_rn(2.0f, m0v)), cnv.x);
                float v1 = __fadd_rn(__fsub_rn(xn[r], __fmul_rn(2.0f, m1v)), cnv.y);
                if (v0 < best[r]) { best[r] = v0; bidx[r] = k0; }
                if (v1 < best[r]) { best[r] = v1; bidx[r] = k0 + 1; }
            }
        }
    }

    // cross-thread reduction: 128 rows x 16 candidates
    __syncthreads();
    float* rv = (float*)&xsp[0][0];    // 2048 floats (fits in 16640 B)
    int*   ri = (int*)&cs[0][0];       // 2048 ints  (fits in  8448 B)
#pragma unroll
    for (int r = 0; r < 8; r++) {
        rv[(tr * 8 + r) * 16 + tc] = best[r];
        ri[(tr * 8 + r) * 16 + tc] = bidx[r];
    }
    __syncthreads();
    if (tid < TM) {
        float bv = rv[tid * 16];
        int bi = ri[tid * 16];
#pragma unroll
        for (int j = 1; j < 16; j++) {
            float v = rv[tid * 16 + j];
            int i2 = ri[tid * 16 + j];
            if (v < bv || (v == bv && i2 < bi)) { bv = v; bi = i2; }
        }
        int b = m0 + tid;
        g_idx[b * Ln + level] = bi;
        out_base[OFF_OUT + (size_t)b * Ln + level] = (float)bi;
        atomicAdd(&g_hist[level * Kn + bi], 1);
    }
}

// ---------------- gather e, compute next residual ----------------
__global__ void update_kernel(const float* __restrict__ cb, float* __restrict__ out, int level) {
    size_t t = (size_t)blockIdx.x * 256 + threadIdx.x;   // B*D/4
    int b = (int)(t >> 7);
    int d4 = ((int)t & 127) << 2;
    int idx = g_idx[b * Ln + level];
    const float* cbl = cb + ((size_t)level * Kn + idx) * Dn;
    float4 e = *(const float4*)(cbl + d4);
    size_t ro = ((size_t)b * Ln + level) * Dn + d4;
    *(float4*)(out + OFF_E + ro) = e;
    if (level < Ln - 1) {
        float4 r = *(const float4*)(out + OFF_R + ro);
        float4 rn = make_float4(__fsub_rn(r.x, e.x), __fsub_rn(r.y, e.y),
                                __fsub_rn(r.z, e.z), __fsub_rn(r.w, e.w));
        *(float4*)(out + OFF_R + ro + Dn) = rn;
    }
}

// ---------------- z_hat = x + (sum_l e_l - x) ----------------
__global__ void zhat_kernel(const float* __restrict__ x, float* __restrict__ out) {
    size_t t = (size_t)blockIdx.x * 256 + threadIdx.x;   // B*D/4
    int b = (int)(t >> 7);
    int d4 = ((int)t & 127) << 2;
    const float* eb = out + OFF_E + (size_t)b * Ln * Dn + d4;
    float4 e0 = *(const float4*)(eb);
    float4 e1 = *(const float4*)(eb + Dn);
    float4 e2 = *(const float4*)(eb + 2 * Dn);
    float4 e3 = *(const float4*)(eb + 3 * Dn);
    float4 xv = *(const float4*)(x + (size_t)b * Dn + d4);
    float4 z;
    z.x = __fadd_rn(xv.x, __fsub_rn(__fadd_rn(__fadd_rn(__fadd_rn(e0.x, e1.x), e2.x), e3.x), xv.x));
    z.y = __fadd_rn(xv.y, __fsub_rn(__fadd_rn(__fadd_rn(__fadd_rn(e0.y, e1.y), e2.y), e3.y), xv.y));
    z.z = __fadd_rn(xv.z, __fsub_rn(__fadd_rn(__fadd_rn(__fadd_rn(e0.z, e1.z), e2.z), e3.z), xv.z));
    z.w = __fadd_rn(xv.w, __fsub_rn(__fadd_rn(__fadd_rn(__fadd_rn(e0.w, e1.w), e2.w), e3.w), xv.w));
    *(float4*)(out + OFF_Z + (size_t)b * Dn + d4) = z;
}

// ---------------- unused-code count ----------------
__global__ void count_kernel(float* __restrict__ out) {
    int t = threadIdx.x;   // 256
    int c = 0;
    for (int i = t; i < Ln * Kn; i += 256)
        if (g_hist[i] == 0) c++;
    for (int o = 16; o; o >>= 1) c += __shfl_down_sync(0xFFFFFFFFu, c, o);
    __shared__ int ws[8];
    if ((t & 31) == 0) ws[t >> 5] = c;
    __syncthreads();
    if (t == 0) {
        int tot = 0;
        for (int j = 0; j < 8; j++) tot += ws[j];
        out[OFF_CNT] = (float)tot;
    }
}

extern "C" void kernel_launch(void* const* d_in, const int* in_sizes, int n_in,
                              void* d_out, int out_size) {
    const float* x  = (const float*)d_in[0];   // [B, D]
    const float* cb = (const float*)d_in[1];   // [L, K, D]
    float* out = (float*)d_out;

    prep_kernel<<<Ln * Kn, 256>>>(cb);
    copy_r0_kernel<<<(Bn * Dn / 4) / 256, 256>>>(x, out);
    for (int l = 0; l < Ln; l++) {
        xnorm_kernel<<<Bn, 256>>>(out, l);
        argmin_kernel<<<Bn / TM, 256>>>(out, cb, l);
        update_kernel<<<(Bn * Dn / 4) / 256, 256>>>(cb, out, l);
    }
    zhat_kernel<<<(Bn * Dn / 4) / 256, 256>>>(x, out);
    count_kernel<<<1, 256>>>(out);
}